// round 1
// baseline (speedup 1.0000x reference)
#include <cuda_runtime.h>
#include <math.h>

// Problem constants (B=1, C=256, H=64, W=96, R=4)
#define Hh 64
#define Ww 96
#define Cc 256
#define HW (Hh * Ww)          // 6144
#define KK 9                   // 2R+1
#define NOUT (KK * KK)         // 81

// Pixel-major scratch copies of the feature maps: f[pixel][channel]
__device__ float g_f1t[HW * Cc];
__device__ float g_f2t[HW * Cc];

// --------------------------------------------------------------------------
// Tiled transpose: [C, HW] (channel-major input) -> [HW, C] (pixel-major)
// which = 0 -> fmap1 scratch, 1 -> fmap2 scratch
// --------------------------------------------------------------------------
__global__ __launch_bounds__(1024) void transpose_kernel(const float* __restrict__ in, int which) {
    __shared__ float tile[32][33];
    float* out = which ? g_f2t : g_f1t;
    int p0 = blockIdx.x * 32;   // pixel tile origin
    int c0 = blockIdx.y * 32;   // channel tile origin
    int tx = threadIdx.x, ty = threadIdx.y;
    // coalesced read along pixel dim
    tile[ty][tx] = in[(c0 + ty) * HW + (p0 + tx)];
    __syncthreads();
    // coalesced write along channel dim
    out[(size_t)(p0 + ty) * Cc + (c0 + tx)] = tile[tx][ty];
}

// --------------------------------------------------------------------------
// Main kernel: one warp per query pixel.
// Phase 1: compute the 10x10 integer corr window (zero outside image) into
//          a zero-guarded 11x11 shared window (stride 12).
// Phase 2: 81 bilinear combines, faithful to the reference:
//          channel k = i*9+j samples at (x = cx + (i-4), y = cy + (j-4)).
// --------------------------------------------------------------------------
__global__ __launch_bounds__(256) void corr_main(const float* __restrict__ coords,
                                                 float* __restrict__ out) {
    __shared__ float win[8][11 * 12];

    const int warp = threadIdx.x >> 5;
    const int lane = threadIdx.x & 31;
    const int q = blockIdx.x * 8 + warp;   // HW = 6144 = 768 blocks * 8 warps

    const float cx = coords[q];            // channel 0 = x
    const float cy = coords[HW + q];       // channel 1 = y
    const int xb = (int)floorf(cx) - 4;    // window x origin
    const int yb = (int)floorf(cy) - 4;    // window y origin

    // Load this query's 256-ch feature vector, 8 floats/lane, coalesced float4s
    const float4* f1 = reinterpret_cast<const float4*>(g_f1t) + (size_t)q * (Cc / 4);
    const float4 a0 = f1[lane];
    const float4 a1 = f1[lane + 32];

    float* w = win[warp];
    #pragma unroll
    for (int i = lane; i < 11 * 12; i += 32) w[i] = 0.0f;
    __syncwarp();

    const float4* f2 = reinterpret_cast<const float4*>(g_f2t);

    #pragma unroll 1
    for (int iy = 0; iy < 10; ++iy) {
        const int yy = yb + iy;
        const bool yok = ((unsigned)yy < (unsigned)Hh);
        #pragma unroll 1
        for (int jx = 0; jx < 10; ++jx) {
            const int xx = xb + jx;
            float s = 0.0f;
            if (yok && (unsigned)xx < (unsigned)Ww) {
                const float4* col = f2 + (size_t)(yy * Ww + xx) * (Cc / 4);
                const float4 b0 = col[lane];
                const float4 b1 = col[lane + 32];
                s = a0.x * b0.x + a0.y * b0.y + a0.z * b0.z + a0.w * b0.w
                  + a1.x * b1.x + a1.y * b1.y + a1.z * b1.z + a1.w * b1.w;
            }
            // warp all-reduce
            #pragma unroll
            for (int o = 16; o; o >>= 1) s += __shfl_xor_sync(0xffffffffu, s, o);
            if (lane == 0) w[iy * 12 + jx] = s * 0.0625f;   // / sqrt(256)
        }
    }
    __syncwarp();

    // Phase 2: bilinear gather of the 81 outputs
    #pragma unroll
    for (int k = lane; k < NOUT; k += 32) {
        const int i = k / KK;          // offsets the X coordinate (meshgrid quirk)
        const int j = k - i * KK;      // offsets the Y coordinate
        const float x = cx + (float)(i - 4);
        const float y = cy + (float)(j - 4);
        const float x0 = floorf(x);
        const float y0 = floorf(y);
        const int ix = (int)x0 - xb;   // 0..10 (10 only on fp slip, weight 0 -> guard)
        const int iw = (int)y0 - yb;   // 0..10
        const float wx1 = x - x0, wy1 = y - y0;
        const float wx0 = 1.0f - wx1, wy0 = 1.0f - wy1;
        const float* r0 = w + iw * 12 + ix;
        const float* r1 = r0 + 12;
        const float v = wy0 * (wx0 * r0[0] + wx1 * r0[1])
                      + wy1 * (wx0 * r1[0] + wx1 * r1[1]);
        out[(size_t)k * HW + q] = v;
    }
}

// --------------------------------------------------------------------------
extern "C" void kernel_launch(void* const* d_in, const int* in_sizes, int n_in,
                              void* d_out, int out_size) {
    const float* fmap1  = (const float*)d_in[0];
    const float* fmap2  = (const float*)d_in[1];
    const float* coords = (const float*)d_in[2];
    float* out = (float*)d_out;

    dim3 tb(32, 32);
    dim3 tg(HW / 32, Cc / 32);
    transpose_kernel<<<tg, tb>>>(fmap1, 0);
    transpose_kernel<<<tg, tb>>>(fmap2, 1);
    corr_main<<<HW / 8, 256>>>(coords, out);
}

// round 2
// speedup vs baseline: 1.2096x; 1.2096x over previous
#include <cuda_runtime.h>
#include <cuda_fp16.h>
#include <math.h>

// Problem constants (B=1, C=256, H=64, W=96, R=4)
#define Hh 64
#define Ww 96
#define Cc 256
#define HW (Hh * Ww)          // 6144
#define KK 9                  // 2R+1
#define NOUT (KK * KK)        // 81

// Pixel-major fp16 copy of fmap2: g_f2h[pixel][channel]
__device__ __half g_f2h[HW * Cc];

// --------------------------------------------------------------------------
// Tiled transpose + fp32->fp16 convert: [C, HW] -> [HW, C] (pixel-major half)
// --------------------------------------------------------------------------
__global__ __launch_bounds__(1024) void transpose_convert(const float* __restrict__ in) {
    __shared__ float tile[32][33];
    int p0 = blockIdx.x * 32;   // pixel tile origin
    int c0 = blockIdx.y * 32;   // channel tile origin
    int tx = threadIdx.x, ty = threadIdx.y;
    tile[ty][tx] = in[(c0 + ty) * HW + (p0 + tx)];   // coalesced along pixels
    __syncthreads();
    g_f2h[(size_t)(p0 + ty) * Cc + (c0 + tx)] = __float2half(tile[tx][ty]);
}

// --------------------------------------------------------------------------
// Main kernel: one warp per query pixel (8 queries per 256-thread block).
// Phase 0: stage the block's 8 fmap1 query vectors (fp32) into shared,
//          loading straight from channel-major layout (sector-coalesced).
// Phase 1: 10x10 integer corr window (zero outside image) into a
//          zero-guarded 11x11 shared window (stride 12). fmap2 in fp16.
// Phase 2: 81 bilinear combines; channel k=i*9+j samples at
//          (x = cx + (i-4), y = cy + (j-4))  [torch meshgrid 'ij' quirk].
// Phase 3: coalesced output store via padded shared staging.
// --------------------------------------------------------------------------
__global__ __launch_bounds__(256) void corr_main(const float* __restrict__ coords,
                                                 const float* __restrict__ fmap1,
                                                 float* __restrict__ out) {
    __shared__ float f1s[8][Cc];        // 8 KB: per-query fp32 feature vectors
    __shared__ float win[8][11 * 12];   // 4.2 KB: per-warp corr windows
    __shared__ float sout[NOUT][9];     // 2.9 KB: padded output staging

    const int t = threadIdx.x;
    const int warp = t >> 5;
    const int lane = t & 31;
    const int q0 = blockIdx.x * 8;

    // ---- Phase 0: stage fmap1 rows (channel-major -> shared pixel-major)
    {
        const int i = t & 7;        // query-in-block
        const int cb = t >> 3;      // channel base 0..31
        #pragma unroll
        for (int c = cb; c < Cc; c += 32)
            f1s[i][c] = fmap1[c * HW + q0 + i];
    }
    __syncthreads();

    const int q = q0 + warp;
    const float cx = coords[q];          // channel 0 = x
    const float cy = coords[HW + q];     // channel 1 = y
    const int xb = (int)floorf(cx) - 4;  // window x origin
    const int yb = (int)floorf(cy) - 4;  // window y origin

    // This lane's 8 channels of the query vector (channels 8*lane .. 8*lane+7)
    const float4* rowf4 = reinterpret_cast<const float4*>(f1s[warp]);
    const float4 a0 = rowf4[2 * lane];
    const float4 a1 = rowf4[2 * lane + 1];

    float* w = win[warp];
    #pragma unroll
    for (int i = lane; i < 11 * 12; i += 32) w[i] = 0.0f;
    __syncwarp();

    // fmap2 columns: 8 halves (16B) per lane
    const uint4* f2 = reinterpret_cast<const uint4*>(g_f2h);

    // ---- Phase 1: 10x10 window of warp-reduced dots
    #pragma unroll 1
    for (int iy = 0; iy < 10; ++iy) {
        const int yy = yb + iy;
        const bool yok = ((unsigned)yy < (unsigned)Hh);
        #pragma unroll 2
        for (int jx = 0; jx < 10; ++jx) {
            const int xx = xb + jx;
            float s = 0.0f;
            if (yok && (unsigned)xx < (unsigned)Ww) {
                const uint4 b = f2[(size_t)(yy * Ww + xx) * (Cc / 8) + lane];
                const float2 p0 = __half22float2(*reinterpret_cast<const __half2*>(&b.x));
                const float2 p1 = __half22float2(*reinterpret_cast<const __half2*>(&b.y));
                const float2 p2 = __half22float2(*reinterpret_cast<const __half2*>(&b.z));
                const float2 p3 = __half22float2(*reinterpret_cast<const __half2*>(&b.w));
                s = a0.x * p0.x + a0.y * p0.y + a0.z * p1.x + a0.w * p1.y
                  + a1.x * p2.x + a1.y * p2.y + a1.z * p3.x + a1.w * p3.y;
            }
            // warp all-reduce
            #pragma unroll
            for (int o = 16; o; o >>= 1) s += __shfl_xor_sync(0xffffffffu, s, o);
            if (lane == 0) w[iy * 12 + jx] = s * 0.0625f;   // / sqrt(256)
        }
    }
    __syncwarp();

    // ---- Phase 2: bilinear gather of the 81 outputs -> staged in shared
    #pragma unroll
    for (int k = lane; k < NOUT; k += 32) {
        const int i = k / KK;          // offsets the X coordinate
        const int j = k - i * KK;      // offsets the Y coordinate
        const float x = cx + (float)(i - 4);
        const float y = cy + (float)(j - 4);
        const float x0 = floorf(x);
        const float y0 = floorf(y);
        const int ix = (int)x0 - xb;   // 0..10 (10 only on fp slip, weight 0)
        const int iw = (int)y0 - yb;   // 0..10
        const float wx1 = x - x0, wy1 = y - y0;
        const float wx0 = 1.0f - wx1, wy0 = 1.0f - wy1;
        const float* r0 = w + iw * 12 + ix;
        const float* r1 = r0 + 12;
        sout[k][warp] = wy0 * (wx0 * r0[0] + wx1 * r0[1])
                      + wy1 * (wx0 * r1[0] + wx1 * r1[1]);
    }
    __syncthreads();

    // ---- Phase 3: coalesced store (8 consecutive q per 32B sector)
    for (int e = t; e < NOUT * 8; e += 256) {
        const int k = e >> 3;
        const int i = e & 7;
        out[(size_t)k * HW + q0 + i] = sout[k][i];
    }
}

// --------------------------------------------------------------------------
extern "C" void kernel_launch(void* const* d_in, const int* in_sizes, int n_in,
                              void* d_out, int out_size) {
    const float* fmap1  = (const float*)d_in[0];
    const float* fmap2  = (const float*)d_in[1];
    const float* coords = (const float*)d_in[2];
    float* out = (float*)d_out;

    dim3 tb(32, 32);
    dim3 tg(HW / 32, Cc / 32);
    transpose_convert<<<tg, tb>>>(fmap2);
    corr_main<<<HW / 8, 256>>>(coords, fmap1, out);
}

// round 3
// speedup vs baseline: 1.4098x; 1.1655x over previous
#include <cuda_runtime.h>
#include <cuda_fp16.h>
#include <math.h>

// Problem constants (B=1, C=256, H=64, W=96, R=4)
#define Hh 64
#define Ww 96
#define Cc 256
#define HW (Hh * Ww)          // 6144
#define KK 9                  // 2R+1
#define NOUT (KK * KK)        // 81

// Pixel-major fp16 copy of fmap2: g_f2h[pixel][channel]
__device__ __half g_f2h[HW * Cc];

// --------------------------------------------------------------------------
// Tiled transpose + fp32->fp16 convert: [C, HW] -> [HW, C] (pixel-major half)
// --------------------------------------------------------------------------
__global__ __launch_bounds__(1024) void transpose_convert(const float* __restrict__ in) {
    __shared__ float tile[32][33];
    int p0 = blockIdx.x * 32;
    int c0 = blockIdx.y * 32;
    int tx = threadIdx.x, ty = threadIdx.y;
    tile[ty][tx] = in[(c0 + ty) * HW + (p0 + tx)];
    __syncthreads();
    g_f2h[(size_t)(p0 + ty) * Cc + (c0 + tx)] = __float2half(tile[tx][ty]);
}

// Accumulate 8 channels: one uint4 of halves against two float4's of the query
#define ACC8(bu, Alo, Ahi, sA, sB) do {                                        \
    float2 q0 = __half22float2(*reinterpret_cast<const __half2*>(&(bu).x));    \
    float2 q1 = __half22float2(*reinterpret_cast<const __half2*>(&(bu).y));    \
    float2 q2 = __half22float2(*reinterpret_cast<const __half2*>(&(bu).z));    \
    float2 q3 = __half22float2(*reinterpret_cast<const __half2*>(&(bu).w));    \
    sA += (Alo).x*q0.x + (Alo).y*q0.y + (Alo).z*q1.x + (Alo).w*q1.y;           \
    sB += (Ahi).x*q2.x + (Ahi).y*q2.y + (Ahi).z*q3.x + (Ahi).w*q3.y;           \
} while (0)

// --------------------------------------------------------------------------
// Main kernel: one warp per query pixel (8 per 256-thread block).
// Phase 1: 25 passes; each pass computes 4 window columns with 8 lanes/column.
//          Lane layout: colsel = lane>>3 (which of the 4 columns),
//          g = lane&7 (channel chunk). Lane g owns channels {8g+64k+j}.
//          uint4 load index g+8k keeps each LDG on one 128B line per column.
// Phase 2: 81 bilinear combines (i offsets x, j offsets y — meshgrid 'ij').
// Phase 3: coalesced store via padded shared staging.
// --------------------------------------------------------------------------
__global__ __launch_bounds__(256) void corr_main(const float* __restrict__ coords,
                                                 const float* __restrict__ fmap1,
                                                 float* __restrict__ out) {
    __shared__ float f1s[8][Cc];        // per-query fp32 feature vectors
    __shared__ float win[8][11 * 12];   // per-warp corr windows (zero-guarded)
    __shared__ float sout[NOUT][9];     // padded output staging

    const int t = threadIdx.x;
    const int warp = t >> 5;
    const int lane = t & 31;
    const int q0 = blockIdx.x * 8;

    // ---- Phase 0: stage fmap1 rows (channel-major -> shared pixel-major)
    {
        const int i = t & 7;
        const int cb = t >> 3;
        #pragma unroll
        for (int c = cb; c < Cc; c += 32)
            f1s[i][c] = fmap1[c * HW + q0 + i];
    }
    __syncthreads();

    const int q = q0 + warp;
    const float cx = coords[q];          // channel 0 = x
    const float cy = coords[HW + q];     // channel 1 = y
    const int xb = (int)floorf(cx) - 4;
    const int yb = (int)floorf(cy) - 4;

    const int g = lane & 7;        // channel chunk
    const int colsel = lane >> 3;  // which column of the 4 in this pass

    // This lane's 32 channels of the query vector: channels 8g + 64k + (0..7)
    float4 A[8];
    {
        const float4* rowf4 = reinterpret_cast<const float4*>(f1s[warp]);
        #pragma unroll
        for (int k = 0; k < 4; ++k) {
            A[2 * k]     = rowf4[2 * g + 16 * k];
            A[2 * k + 1] = rowf4[2 * g + 16 * k + 1];
        }
    }

    float* w = win[warp];
    #pragma unroll
    for (int i = lane; i < 11 * 12; i += 32) w[i] = 0.0f;
    __syncwarp();

    const uint4* f2 = reinterpret_cast<const uint4*>(g_f2h);

    // ---- Phase 1: 10x10 window, 4 columns per pass
    #pragma unroll 1
    for (int p = 0; p < 25; ++p) {
        const int c  = 4 * p + colsel;       // 0..99
        const int iy = c / 10;
        const int jx = c - iy * 10;
        const int yy = yb + iy;
        const int xx = xb + jx;
        const bool ok = ((unsigned)yy < (unsigned)Hh) & ((unsigned)xx < (unsigned)Ww);
        const int yc = min(max(yy, 0), Hh - 1);
        const int xc = min(max(xx, 0), Ww - 1);
        const uint4* col = f2 + (size_t)(yc * Ww + xc) * (Cc / 8) + g;

        const uint4 b0 = col[0];
        const uint4 b1 = col[8];
        const uint4 b2 = col[16];
        const uint4 b3 = col[24];

        float s0 = 0.f, s1 = 0.f, s2 = 0.f, s3 = 0.f;
        ACC8(b0, A[0], A[1], s0, s1);
        ACC8(b1, A[2], A[3], s2, s3);
        ACC8(b2, A[4], A[5], s0, s1);
        ACC8(b3, A[6], A[7], s2, s3);

        float s = (s0 + s1) + (s2 + s3);
        s = ok ? s : 0.0f;
        // reduce across the 8 lanes of this column group
        s += __shfl_xor_sync(0xffffffffu, s, 1);
        s += __shfl_xor_sync(0xffffffffu, s, 2);
        s += __shfl_xor_sync(0xffffffffu, s, 4);
        if (g == 0) w[iy * 12 + jx] = s * 0.0625f;   // / sqrt(256)
    }
    __syncwarp();

    // ---- Phase 2: bilinear gather of the 81 outputs -> staged in shared
    #pragma unroll
    for (int k = lane; k < NOUT; k += 32) {
        const int i = k / KK;          // offsets the X coordinate
        const int j = k - i * KK;      // offsets the Y coordinate
        const float x = cx + (float)(i - 4);
        const float y = cy + (float)(j - 4);
        const float x0 = floorf(x);
        const float y0 = floorf(y);
        const int ix = (int)x0 - xb;   // 0..8 (exact fp32 integer adds)
        const int iw = (int)y0 - yb;   // 0..8
        const float wx1 = x - x0, wy1 = y - y0;
        const float wx0 = 1.0f - wx1, wy0 = 1.0f - wy1;
        const float* r0 = w + iw * 12 + ix;
        const float* r1 = r0 + 12;
        sout[k][warp] = wy0 * (wx0 * r0[0] + wx1 * r0[1])
                      + wy1 * (wx0 * r1[0] + wx1 * r1[1]);
    }
    __syncthreads();

    // ---- Phase 3: coalesced store (8 consecutive q per 32B sector)
    for (int e = t; e < NOUT * 8; e += 256) {
        const int k = e >> 3;
        const int i = e & 7;
        out[(size_t)k * HW + q0 + i] = sout[k][i];
    }
}

// --------------------------------------------------------------------------
extern "C" void kernel_launch(void* const* d_in, const int* in_sizes, int n_in,
                              void* d_out, int out_size) {
    const float* fmap1  = (const float*)d_in[0];
    const float* fmap2  = (const float*)d_in[1];
    const float* coords = (const float*)d_in[2];
    float* out = (float*)d_out;

    dim3 tb(32, 32);
    dim3 tg(HW / 32, Cc / 32);
    transpose_convert<<<tg, tb>>>(fmap2);
    corr_main<<<HW / 8, 256>>>(coords, fmap1, out);
}